// round 7
// baseline (speedup 1.0000x reference)
#include <cuda_runtime.h>
#include <cuda_bf16.h>
#include <mma.h>
#include <cstdint>

using namespace nvcuda;

#define DIM 128
#define NMAX 50000
#define EMAX 800000
#define BN_EPS 1e-5f
#define SCAN_CHUNK 4096

// ---------------- scratch (allocation-free) ----------------
__device__ float g_buf0[NMAX * DIM];
__device__ float g_buf1[NMAX * DIM];
__device__ int   g_deg[NMAX + 1];
__device__ int   g_off[NMAX + 1];
__device__ int   g_cur[NMAX];
__device__ int   g_csr[EMAX];
__device__ int   g_excl[NMAX];
__device__ int   g_bsum[64];
__device__ int   g_boff[64];
__device__ __nv_bfloat16 g_wt_hi[6 * DIM * DIM];  // transposed: [w][j][k]
__device__ __nv_bfloat16 g_wt_lo[6 * DIM * DIM];

// ---------------- CSR build ----------------
__global__ void zero_deg_kernel(int* __restrict__ deg, int n) {
    int i = blockIdx.x * blockDim.x + threadIdx.x;
    if (i <= n) deg[i] = 0;
}

__global__ void hist_kernel(const int* __restrict__ dst, int* __restrict__ deg, int e) {
    int i = blockIdx.x * blockDim.x + threadIdx.x;
    if (i < e) atomicAdd(&deg[dst[i]], 1);
}

// multi-block scan, stage 1: per-block exclusive prefix + block sum.
// Each block covers SCAN_CHUNK elems (4 per thread).
__global__ void scan1_kernel(const int* __restrict__ deg, int* __restrict__ excl,
                             int* __restrict__ bsum, int n) {
    __shared__ int wsum[32];
    int tid = threadIdx.x;
    int lane = tid & 31;
    int w = tid >> 5;
    int idx = blockIdx.x * SCAN_CHUNK + tid * 4;

    int v0 = 0, v1 = 0, v2 = 0, v3 = 0;
    if (idx + 3 < n) {
        int4 q = *(const int4*)(deg + idx);
        v0 = q.x; v1 = q.y; v2 = q.z; v3 = q.w;
    } else {
        if (idx + 0 < n) v0 = deg[idx + 0];
        if (idx + 1 < n) v1 = deg[idx + 1];
        if (idx + 2 < n) v2 = deg[idx + 2];
        if (idx + 3 < n) v3 = deg[idx + 3];
    }
    int t = v0 + v1 + v2 + v3;

    // warp inclusive scan of per-thread totals
    int s = t;
#pragma unroll
    for (int d = 1; d < 32; d <<= 1) {
        int u = __shfl_up_sync(0xFFFFFFFFu, s, d);
        if (lane >= d) s += u;
    }
    if (lane == 31) wsum[w] = s;
    __syncthreads();
    if (w == 0) {
        int ws = wsum[lane];
#pragma unroll
        for (int d = 1; d < 32; d <<= 1) {
            int u = __shfl_up_sync(0xFFFFFFFFu, ws, d);
            if (lane >= d) ws += u;
        }
        wsum[lane] = ws;
    }
    __syncthreads();

    int warp_off = (w > 0) ? wsum[w - 1] : 0;
    int te = warp_off + s - t;   // exclusive prefix for this thread's first elem

    if (idx + 0 < n) excl[idx + 0] = te;
    if (idx + 1 < n) excl[idx + 1] = te + v0;
    if (idx + 2 < n) excl[idx + 2] = te + v0 + v1;
    if (idx + 3 < n) excl[idx + 3] = te + v0 + v1 + v2;

    if (tid == 0) bsum[blockIdx.x] = wsum[31];
}

// stage 2: single warp scans block sums (exclusive), writes total into off[n]
__global__ void scan2_kernel(const int* __restrict__ bsum, int* __restrict__ boff,
                             int* __restrict__ off, int nblocks, int n) {
    int lane = threadIdx.x;
    int v = (lane < nblocks) ? bsum[lane] : 0;
    int s = v;
#pragma unroll
    for (int d = 1; d < 32; d <<= 1) {
        int u = __shfl_up_sync(0xFFFFFFFFu, s, d);
        if (lane >= d) s += u;
    }
    if (lane < nblocks) boff[lane] = s - v;
    if (lane == 31) off[n] = s;  // total (nblocks <= 32)
}

// stage 3: add block offsets, write off + cur
__global__ void scan3_kernel(const int* __restrict__ excl, const int* __restrict__ boff,
                             int* __restrict__ off, int* __restrict__ cur, int n) {
    int i = blockIdx.x * blockDim.x + threadIdx.x;
    if (i < n) {
        int o = excl[i] + boff[i / SCAN_CHUNK];
        off[i] = o;
        cur[i] = o;
    }
}

__global__ void fill_kernel(const int* __restrict__ src, const int* __restrict__ dst,
                            int* __restrict__ cur, int* __restrict__ csr, int e) {
    int i = blockIdx.x * blockDim.x + threadIdx.x;
    if (i < e) {
        int pos = atomicAdd(&cur[dst[i]], 1);
        csr[pos] = src[i];
    }
}

// ---------------- weight prep: transpose + bf16 hi/lo split ----------------
__global__ void prep_w_kernel(const float* __restrict__ W1, const float* __restrict__ W2) {
    int idx = blockIdx.x * blockDim.x + threadIdx.x;
    if (idx >= 6 * DIM * DIM) return;
    int w = idx >> 14;
    int r = idx & 16383;
    int k = r >> 7;
    int j = r & 127;
    const float* srcm = (w & 1) ? W2 : W1;
    float v = srcm[((size_t)(w >> 1) << 14) + (k << 7) + j];
    __nv_bfloat16 hi = __float2bfloat16(v);
    __nv_bfloat16 lo = __float2bfloat16(v - __bfloat162float(hi));
    int dst = (w << 14) + (j << 7) + k;
    g_wt_hi[dst] = hi;
    g_wt_lo[dst] = lo;
}

// ---------------- gather: out[n] = h[n] + sum h[csr[n]] ----------------
__global__ void gather_kernel(const float* __restrict__ h,
                              const int* __restrict__ off,
                              const int* __restrict__ csr,
                              float* __restrict__ out, int n) {
    int warp = (blockIdx.x * blockDim.x + threadIdx.x) >> 5;
    int lane = threadIdx.x & 31;
    if (warp >= n) return;
    int beg = off[warp];
    int end = off[warp + 1];
    size_t c = (size_t)lane * 4;

    float4 acc = *(const float4*)(h + (size_t)warp * DIM + c);
    int i = beg;
    for (; i + 4 <= end; i += 4) {
        int s0 = __ldg(csr + i);
        int s1 = __ldg(csr + i + 1);
        int s2 = __ldg(csr + i + 2);
        int s3 = __ldg(csr + i + 3);
        float4 a = *(const float4*)(h + (size_t)s0 * DIM + c);
        float4 b = *(const float4*)(h + (size_t)s1 * DIM + c);
        float4 d = *(const float4*)(h + (size_t)s2 * DIM + c);
        float4 f = *(const float4*)(h + (size_t)s3 * DIM + c);
        acc.x += a.x + b.x + d.x + f.x;
        acc.y += a.y + b.y + d.y + f.y;
        acc.z += a.z + b.z + d.z + f.z;
        acc.w += a.w + b.w + d.w + f.w;
    }
    for (; i < end; i++) {
        int s = __ldg(csr + i);
        float4 a = *(const float4*)(h + (size_t)s * DIM + c);
        acc.x += a.x; acc.y += a.y; acc.z += a.z; acc.w += a.w;
    }
    *(float4*)(out + (size_t)warp * DIM + c) = acc;
}

// ---------------- wmma bf16x3 GEMM + bias + BN + ReLU ----------------
#define LDA 136
#define A_BYTES (128 * LDA * 2)
#define OFF_AHI 0
#define OFF_ALO (OFF_AHI + A_BYTES)
#define OFF_BHI (OFF_ALO + A_BYTES)
#define OFF_BLO (OFF_BHI + A_BYTES)
#define SMEM_TOTAL (OFF_BLO + A_BYTES)
#define OFF_STG OFF_BHI

__global__ void __launch_bounds__(256, 1)
gemm_wmma_kernel(const float* __restrict__ A,
                 const __nv_bfloat16* __restrict__ Bt_hi,
                 const __nv_bfloat16* __restrict__ Bt_lo,
                 const float* __restrict__ bias,
                 const float* __restrict__ gamma,
                 const float* __restrict__ beta,
                 const float* __restrict__ mean,
                 const float* __restrict__ var,
                 float* __restrict__ out, int nrows) {
    extern __shared__ char smem[];
    __nv_bfloat16* Ahi = (__nv_bfloat16*)(smem + OFF_AHI);
    __nv_bfloat16* Alo = (__nv_bfloat16*)(smem + OFF_ALO);
    __nv_bfloat16* Bhi = (__nv_bfloat16*)(smem + OFF_BHI);
    __nv_bfloat16* Blo = (__nv_bfloat16*)(smem + OFF_BLO);

    int tid = threadIdx.x;
    int wid = tid >> 5;
    int lane = tid & 31;
    int row0 = blockIdx.x * 128;

    {
        const uint4* shi = (const uint4*)Bt_hi;
        const uint4* slo = (const uint4*)Bt_lo;
#pragma unroll
        for (int i = tid; i < 2048; i += 256) {
            int j = i >> 4;
            int k8 = (i & 15) << 3;
            uint32_t o = (uint32_t)(j * LDA + k8);
            *(uint4*)(Bhi + o) = shi[i];
            *(uint4*)(Blo + o) = slo[i];
        }
    }
    {
#pragma unroll
        for (int i = tid; i < 4096; i += 256) {
            int r = i >> 5;
            int k4 = (i & 31) << 2;
            float4 v = make_float4(0.f, 0.f, 0.f, 0.f);
            if (row0 + r < nrows)
                v = ((const float4*)(A + (size_t)(row0 + r) * DIM))[i & 31];
            __nv_bfloat16 h0 = __float2bfloat16(v.x), h1 = __float2bfloat16(v.y);
            __nv_bfloat16 h2 = __float2bfloat16(v.z), h3 = __float2bfloat16(v.w);
            __nv_bfloat16 l0 = __float2bfloat16(v.x - __bfloat162float(h0));
            __nv_bfloat16 l1 = __float2bfloat16(v.y - __bfloat162float(h1));
            __nv_bfloat16 l2 = __float2bfloat16(v.z - __bfloat162float(h2));
            __nv_bfloat16 l3 = __float2bfloat16(v.w - __bfloat162float(h3));
            __nv_bfloat162 hA(h0, h1), hB(h2, h3), lA(l0, l1), lB(l2, l3);
            uint32_t o = (uint32_t)(r * LDA + k4);
            *(uint2*)(Ahi + o) = make_uint2(*(uint32_t*)&hA, *(uint32_t*)&hB);
            *(uint2*)(Alo + o) = make_uint2(*(uint32_t*)&lA, *(uint32_t*)&lB);
        }
    }
    __syncthreads();

    wmma::fragment<wmma::accumulator, 16, 16, 16, float> c[8];
#pragma unroll
    for (int n = 0; n < 8; n++) wmma::fill_fragment(c[n], 0.0f);

    const __nv_bfloat16* arow_hi = Ahi + wid * 16 * LDA;
    const __nv_bfloat16* arow_lo = Alo + wid * 16 * LDA;

#pragma unroll
    for (int k0 = 0; k0 < 8; k0++) {
        wmma::fragment<wmma::matrix_a, 16, 16, 16, __nv_bfloat16, wmma::row_major> ahi, alo;
        wmma::load_matrix_sync(ahi, arow_hi + k0 * 16, LDA);
        wmma::load_matrix_sync(alo, arow_lo + k0 * 16, LDA);
#pragma unroll
        for (int n = 0; n < 8; n++) {
            wmma::fragment<wmma::matrix_b, 16, 16, 16, __nv_bfloat16, wmma::col_major> bhi, blo;
            wmma::load_matrix_sync(bhi, Bhi + n * 16 * LDA + k0 * 16, LDA);
            wmma::load_matrix_sync(blo, Blo + n * 16 * LDA + k0 * 16, LDA);
            wmma::mma_sync(c[n], ahi, bhi, c[n]);
            wmma::mma_sync(c[n], ahi, blo, c[n]);
            wmma::mma_sync(c[n], alo, bhi, c[n]);
        }
    }

    __syncthreads();

    float* stg = (float*)(smem + OFF_STG) + wid * (16 * LDA);
#pragma unroll
    for (int n = 0; n < 8; n++)
        wmma::store_matrix_sync(stg + n * 16, c[n], LDA, wmma::mem_row_major);

    int col = lane * 4;
    float4 gm = *(const float4*)(gamma + col);
    float4 vr = *(const float4*)(var + col);
    float4 bt = *(const float4*)(beta + col);
    float4 mn = *(const float4*)(mean + col);
    float4 bs = *(const float4*)(bias + col);
    float4 sc4, sh4;
    sc4.x = gm.x * rsqrtf(vr.x + BN_EPS);
    sc4.y = gm.y * rsqrtf(vr.y + BN_EPS);
    sc4.z = gm.z * rsqrtf(vr.z + BN_EPS);
    sc4.w = gm.w * rsqrtf(vr.w + BN_EPS);
    sh4.x = bt.x - mn.x * sc4.x + bs.x * sc4.x;
    sh4.y = bt.y - mn.y * sc4.y + bs.y * sc4.y;
    sh4.z = bt.z - mn.z * sc4.z + bs.z * sc4.z;
    sh4.w = bt.w - mn.w * sc4.w + bs.w * sc4.w;

    int rbase = row0 + wid * 16;
#pragma unroll
    for (int r = 0; r < 16; r++) {
        int row = rbase + r;
        if (row < nrows) {
            float4 v = *(const float4*)(stg + r * LDA + col);
            v.x = fmaxf(fmaf(v.x, sc4.x, sh4.x), 0.f);
            v.y = fmaxf(fmaf(v.y, sc4.y, sh4.y), 0.f);
            v.z = fmaxf(fmaf(v.z, sc4.z, sh4.z), 0.f);
            v.w = fmaxf(fmaf(v.w, sc4.w, sh4.w), 0.f);
            *(float4*)(out + (size_t)row * DIM + col) = v;
        }
    }
}

// ---------------- launch ----------------
extern "C" void kernel_launch(void* const* d_in, const int* in_sizes, int n_in,
                              void* d_out, int out_size) {
    const float* x  = (const float*)d_in[0];
    const int*   ei = (const int*)d_in[1];
    const float* W1 = (const float*)d_in[2];
    const float* b1 = (const float*)d_in[3];
    const float* W2 = (const float*)d_in[4];
    const float* b2 = (const float*)d_in[5];
    const float* g  = (const float*)d_in[6];
    const float* be = (const float*)d_in[7];
    const float* rm = (const float*)d_in[8];
    const float* rv = (const float*)d_in[9];

    int N = in_sizes[0] / DIM;
    int E = in_sizes[1] / 2;
    const int* src = ei;
    const int* dst = ei + E;
    float* out = (float*)d_out;

    float *buf0, *buf1;
    int *deg, *off, *cur, *csr, *excl, *bsum, *boff;
    __nv_bfloat16 *wth, *wtl;
    cudaGetSymbolAddress((void**)&buf0, g_buf0);
    cudaGetSymbolAddress((void**)&buf1, g_buf1);
    cudaGetSymbolAddress((void**)&deg, g_deg);
    cudaGetSymbolAddress((void**)&off, g_off);
    cudaGetSymbolAddress((void**)&cur, g_cur);
    cudaGetSymbolAddress((void**)&csr, g_csr);
    cudaGetSymbolAddress((void**)&excl, g_excl);
    cudaGetSymbolAddress((void**)&bsum, g_bsum);
    cudaGetSymbolAddress((void**)&boff, g_boff);
    cudaGetSymbolAddress((void**)&wth, g_wt_hi);
    cudaGetSymbolAddress((void**)&wtl, g_wt_lo);

    cudaFuncSetAttribute(gemm_wmma_kernel,
                         cudaFuncAttributeMaxDynamicSharedMemorySize, SMEM_TOTAL);

    // weight prep + CSR build
    prep_w_kernel<<<(6 * DIM * DIM + 255) / 256, 256>>>(W1, W2);
    zero_deg_kernel<<<(N + 256) / 256, 256>>>(deg, N);
    hist_kernel<<<(E + 255) / 256, 256>>>(dst, deg, E);
    int nsb = (N + SCAN_CHUNK - 1) / SCAN_CHUNK;   // <= 32 for N <= 131072
    scan1_kernel<<<nsb, 1024>>>(deg, excl, bsum, N);
    scan2_kernel<<<1, 32>>>(bsum, boff, off, nsb, N);
    scan3_kernel<<<(N + 255) / 256, 256>>>(excl, boff, off, cur, N);
    fill_kernel<<<(E + 255) / 256, 256>>>(src, dst, cur, csr, E);

    // layers (ping-pong)
    const float* hs[3] = {x, buf0, buf1};
    float* aggs[3]     = {buf0, buf1, buf0};
    float* o1s[3]      = {buf1, buf0, buf1};
    float* o2s[3]      = {buf0, buf1, out};

    dim3 gaGrid((N * 32 + 255) / 256);
    dim3 gmGrid((N + 127) / 128);

    for (int i = 0; i < 3; i++) {
        gather_kernel<<<gaGrid, 256>>>(hs[i], off, csr, aggs[i], N);

        int w1i = 2 * i, w2i = 2 * i + 1;
        gemm_wmma_kernel<<<gmGrid, 256, SMEM_TOTAL>>>(
            aggs[i], wth + (size_t)w1i * DIM * DIM, wtl + (size_t)w1i * DIM * DIM,
            b1 + (size_t)i * DIM,
            g  + (size_t)(2 * i + 0) * DIM, be + (size_t)(2 * i + 0) * DIM,
            rm + (size_t)(2 * i + 0) * DIM, rv + (size_t)(2 * i + 0) * DIM,
            o1s[i], N);

        gemm_wmma_kernel<<<gmGrid, 256, SMEM_TOTAL>>>(
            o1s[i], wth + (size_t)w2i * DIM * DIM, wtl + (size_t)w2i * DIM * DIM,
            b2 + (size_t)i * DIM,
            g  + (size_t)(2 * i + 1) * DIM, be + (size_t)(2 * i + 1) * DIM,
            rm + (size_t)(2 * i + 1) * DIM, rv + (size_t)(2 * i + 1) * DIM,
            o2s[i], N);
    }
}

// round 8
// speedup vs baseline: 1.5247x; 1.5247x over previous
#include <cuda_runtime.h>
#include <cuda_bf16.h>
#include <mma.h>
#include <cstdint>

using namespace nvcuda;

#define DIM 128
#define NMAX 50000
#define EMAX 800000
#define BN_EPS 1e-5f
#define SCAN_CHUNK 4096

// ---------------- scratch (allocation-free) ----------------
__device__ float g_buf0[NMAX * DIM];
__device__ float g_buf1[NMAX * DIM];
__device__ int   g_deg[NMAX + 1];
__device__ int   g_off[NMAX + 1];
__device__ int   g_cur[NMAX];
__device__ int   g_csr[EMAX];
__device__ int   g_excl[NMAX];
__device__ int   g_bsum[64];
__device__ int   g_boff[64];
__device__ __nv_bfloat16 g_wt_hi[6 * DIM * DIM];  // transposed: [w][j][k]
__device__ __nv_bfloat16 g_wt_lo[6 * DIM * DIM];

// ---------------- CSR build ----------------
__global__ void zero_deg_kernel(int* __restrict__ deg, int n) {
    int i = blockIdx.x * blockDim.x + threadIdx.x;
    if (i <= n) deg[i] = 0;
}

__global__ void hist_kernel(const int* __restrict__ dst, int* __restrict__ deg, int e) {
    int i = blockIdx.x * blockDim.x + threadIdx.x;
    if (i < e) atomicAdd(&deg[dst[i]], 1);
}

__global__ void scan1_kernel(const int* __restrict__ deg, int* __restrict__ excl,
                             int* __restrict__ bsum, int n) {
    __shared__ int wsum[32];
    int tid = threadIdx.x;
    int lane = tid & 31;
    int w = tid >> 5;
    int idx = blockIdx.x * SCAN_CHUNK + tid * 4;

    int v0 = 0, v1 = 0, v2 = 0, v3 = 0;
    if (idx + 3 < n) {
        int4 q = *(const int4*)(deg + idx);
        v0 = q.x; v1 = q.y; v2 = q.z; v3 = q.w;
    } else {
        if (idx + 0 < n) v0 = deg[idx + 0];
        if (idx + 1 < n) v1 = deg[idx + 1];
        if (idx + 2 < n) v2 = deg[idx + 2];
        if (idx + 3 < n) v3 = deg[idx + 3];
    }
    int t = v0 + v1 + v2 + v3;

    int s = t;
#pragma unroll
    for (int d = 1; d < 32; d <<= 1) {
        int u = __shfl_up_sync(0xFFFFFFFFu, s, d);
        if (lane >= d) s += u;
    }
    if (lane == 31) wsum[w] = s;
    __syncthreads();
    if (w == 0) {
        int ws = wsum[lane];
#pragma unroll
        for (int d = 1; d < 32; d <<= 1) {
            int u = __shfl_up_sync(0xFFFFFFFFu, ws, d);
            if (lane >= d) ws += u;
        }
        wsum[lane] = ws;
    }
    __syncthreads();

    int warp_off = (w > 0) ? wsum[w - 1] : 0;
    int te = warp_off + s - t;

    if (idx + 0 < n) excl[idx + 0] = te;
    if (idx + 1 < n) excl[idx + 1] = te + v0;
    if (idx + 2 < n) excl[idx + 2] = te + v0 + v1;
    if (idx + 3 < n) excl[idx + 3] = te + v0 + v1 + v2;

    if (tid == 0) bsum[blockIdx.x] = wsum[31];
}

__global__ void scan2_kernel(const int* __restrict__ bsum, int* __restrict__ boff,
                             int* __restrict__ off, int nblocks, int n) {
    int lane = threadIdx.x;
    int v = (lane < nblocks) ? bsum[lane] : 0;
    int s = v;
#pragma unroll
    for (int d = 1; d < 32; d <<= 1) {
        int u = __shfl_up_sync(0xFFFFFFFFu, s, d);
        if (lane >= d) s += u;
    }
    if (lane < nblocks) boff[lane] = s - v;
    if (lane == 31) off[n] = s;
}

__global__ void scan3_kernel(const int* __restrict__ excl, const int* __restrict__ boff,
                             int* __restrict__ off, int* __restrict__ cur, int n) {
    int i = blockIdx.x * blockDim.x + threadIdx.x;
    if (i < n) {
        int o = excl[i] + boff[i / SCAN_CHUNK];
        off[i] = o;
        cur[i] = o;
    }
}

__global__ void fill_kernel(const int* __restrict__ src, const int* __restrict__ dst,
                            int* __restrict__ cur, int* __restrict__ csr, int e) {
    int i = blockIdx.x * blockDim.x + threadIdx.x;
    if (i < e) {
        int pos = atomicAdd(&cur[dst[i]], 1);
        csr[pos] = src[i];
    }
}

// ---------------- weight prep: transpose + bf16 hi/lo split ----------------
__global__ void prep_w_kernel(const float* __restrict__ W1, const float* __restrict__ W2) {
    int idx = blockIdx.x * blockDim.x + threadIdx.x;
    if (idx >= 6 * DIM * DIM) return;
    int w = idx >> 14;
    int r = idx & 16383;
    int k = r >> 7;
    int j = r & 127;
    const float* srcm = (w & 1) ? W2 : W1;
    float v = srcm[((size_t)(w >> 1) << 14) + (k << 7) + j];
    __nv_bfloat16 hi = __float2bfloat16(v);
    __nv_bfloat16 lo = __float2bfloat16(v - __bfloat162float(hi));
    int dst = (w << 14) + (j << 7) + k;
    g_wt_hi[dst] = hi;
    g_wt_lo[dst] = lo;
}

// ---------------- shared GEMM machinery ----------------
#define LDA 136
#define LDAF 136
#define A_BYTES (128 * LDA * 2)
#define OFF_AHI 0
#define OFF_ALO (OFF_AHI + A_BYTES)
#define OFF_BHI (OFF_ALO + A_BYTES)
#define OFF_BLO (OFF_BHI + A_BYTES)
#define SMEM_TOTAL (OFF_BLO + A_BYTES)
#define OFF_STG OFF_BHI
#define NTHREADS 512

// split a float4 to bf16 hi/lo packed words
__device__ __forceinline__ void split4(float4 v, uint2& hw, uint2& lw) {
    __nv_bfloat16 h0 = __float2bfloat16(v.x), h1 = __float2bfloat16(v.y);
    __nv_bfloat16 h2 = __float2bfloat16(v.z), h3 = __float2bfloat16(v.w);
    __nv_bfloat16 l0 = __float2bfloat16(v.x - __bfloat162float(h0));
    __nv_bfloat16 l1 = __float2bfloat16(v.y - __bfloat162float(h1));
    __nv_bfloat16 l2 = __float2bfloat16(v.z - __bfloat162float(h2));
    __nv_bfloat16 l3 = __float2bfloat16(v.w - __bfloat162float(h3));
    __nv_bfloat162 hA(h0, h1), hB(h2, h3), lA(l0, l1), lB(l2, l3);
    hw = make_uint2(*(uint32_t*)&hA, *(uint32_t*)&hB);
    lw = make_uint2(*(uint32_t*)&lA, *(uint32_t*)&lB);
}

// Stage B tiles (pre-split, [j][k] layout), mainloop and epilogue shared via
// a macro-free inline pattern: we just write both kernels explicitly.

__device__ __forceinline__ void gemm_mainloop_epilogue(
    char* smem, int tid, int row0, int nrows,
    const float* bias, const float* gamma, const float* beta,
    const float* mean, const float* var, float* out) {

    __nv_bfloat16* Ahi = (__nv_bfloat16*)(smem + OFF_AHI);
    __nv_bfloat16* Alo = (__nv_bfloat16*)(smem + OFF_ALO);
    __nv_bfloat16* Bhi = (__nv_bfloat16*)(smem + OFF_BHI);
    __nv_bfloat16* Blo = (__nv_bfloat16*)(smem + OFF_BLO);

    int w = tid >> 5;
    int mrow = (w & 7) * 16;
    int nbase = (w >> 3) * 64;

    wmma::fragment<wmma::accumulator, 16, 16, 16, float> c[4];
#pragma unroll
    for (int n = 0; n < 4; n++) wmma::fill_fragment(c[n], 0.0f);

    const __nv_bfloat16* arow_hi = Ahi + mrow * LDA;
    const __nv_bfloat16* arow_lo = Alo + mrow * LDA;

#pragma unroll
    for (int k0 = 0; k0 < 8; k0++) {
        wmma::fragment<wmma::matrix_a, 16, 16, 16, __nv_bfloat16, wmma::row_major> ahi, alo;
        wmma::load_matrix_sync(ahi, arow_hi + k0 * 16, LDA);
        wmma::load_matrix_sync(alo, arow_lo + k0 * 16, LDA);
#pragma unroll
        for (int n = 0; n < 4; n++) {
            wmma::fragment<wmma::matrix_b, 16, 16, 16, __nv_bfloat16, wmma::col_major> bhi, blo;
            wmma::load_matrix_sync(bhi, Bhi + (nbase + n * 16) * LDA + k0 * 16, LDA);
            wmma::load_matrix_sync(blo, Blo + (nbase + n * 16) * LDA + k0 * 16, LDA);
            wmma::mma_sync(c[n], ahi, bhi, c[n]);
            wmma::mma_sync(c[n], ahi, blo, c[n]);
            wmma::mma_sync(c[n], alo, bhi, c[n]);
        }
    }

    __syncthreads();  // all warps done reading B before staging reuses it

    float* stg = (float*)(smem + OFF_STG);
#pragma unroll
    for (int n = 0; n < 4; n++)
        wmma::store_matrix_sync(stg + mrow * LDAF + nbase + n * 16, c[n],
                                LDAF, wmma::mem_row_major);
    __syncthreads();

    int u = tid & 31;
    int col = u * 4;
    float4 gm = *(const float4*)(gamma + col);
    float4 vr = *(const float4*)(var + col);
    float4 bt = *(const float4*)(beta + col);
    float4 mn = *(const float4*)(mean + col);
    float4 bs = *(const float4*)(bias + col);
    float4 sc4, sh4;
    sc4.x = gm.x * rsqrtf(vr.x + BN_EPS);
    sc4.y = gm.y * rsqrtf(vr.y + BN_EPS);
    sc4.z = gm.z * rsqrtf(vr.z + BN_EPS);
    sc4.w = gm.w * rsqrtf(vr.w + BN_EPS);
    sh4.x = bt.x - mn.x * sc4.x + bs.x * sc4.x;
    sh4.y = bt.y - mn.y * sc4.y + bs.y * sc4.y;
    sh4.z = bt.z - mn.z * sc4.z + bs.z * sc4.z;
    sh4.w = bt.w - mn.w * sc4.w + bs.w * sc4.w;

#pragma unroll
    for (int i = tid; i < 4096; i += NTHREADS) {
        int row = i >> 5;
        if (row0 + row < nrows) {
            float4 v = *(const float4*)(stg + row * LDAF + col);
            v.x = fmaxf(fmaf(v.x, sc4.x, sh4.x), 0.f);
            v.y = fmaxf(fmaf(v.y, sc4.y, sh4.y), 0.f);
            v.z = fmaxf(fmaf(v.z, sc4.z, sh4.z), 0.f);
            v.w = fmaxf(fmaf(v.w, sc4.w, sh4.w), 0.f);
            *(float4*)(out + (size_t)(row0 + row) * DIM + col) = v;
        }
    }
}

__device__ __forceinline__ void stage_B(char* smem, int tid,
                                        const __nv_bfloat16* Bt_hi,
                                        const __nv_bfloat16* Bt_lo) {
    __nv_bfloat16* Bhi = (__nv_bfloat16*)(smem + OFF_BHI);
    __nv_bfloat16* Blo = (__nv_bfloat16*)(smem + OFF_BLO);
    const uint4* shi = (const uint4*)Bt_hi;
    const uint4* slo = (const uint4*)Bt_lo;
#pragma unroll
    for (int i = tid; i < 2048; i += NTHREADS) {
        int j = i >> 4;
        int k8 = (i & 15) << 3;
        uint32_t o = (uint32_t)(j * LDA + k8);
        *(uint4*)(Bhi + o) = shi[i];
        *(uint4*)(Blo + o) = slo[i];
    }
}

// ---------------- GEMM1: fused CSR gather + wmma bf16x3 + BN + ReLU ----------
__global__ void __launch_bounds__(NTHREADS, 1)
gemm1_fused_kernel(const float* __restrict__ h,
                   const int* __restrict__ off,
                   const int* __restrict__ csr,
                   const __nv_bfloat16* __restrict__ Bt_hi,
                   const __nv_bfloat16* __restrict__ Bt_lo,
                   const float* __restrict__ bias,
                   const float* __restrict__ gamma,
                   const float* __restrict__ beta,
                   const float* __restrict__ mean,
                   const float* __restrict__ var,
                   float* __restrict__ out, int nrows) {
    extern __shared__ char smem[];
    __nv_bfloat16* Ahi = (__nv_bfloat16*)(smem + OFF_AHI);
    __nv_bfloat16* Alo = (__nv_bfloat16*)(smem + OFF_ALO);

    int tid = threadIdx.x;
    int w = tid >> 5;
    int lane = tid & 31;
    int row0 = blockIdx.x * 128;

    stage_B(smem, tid, Bt_hi, Bt_lo);

    // fused gather: warp w stages rows [w*8, w*8+8)
    size_t cb = (size_t)lane * 4;
#pragma unroll
    for (int rr = 0; rr < 8; rr++) {
        int r = w * 8 + rr;
        int node = row0 + r;
        float4 acc = make_float4(0.f, 0.f, 0.f, 0.f);
        if (node < nrows) {
            acc = *(const float4*)(h + (size_t)node * DIM + cb);
            int beg = off[node];
            int end = off[node + 1];
            int i = beg;
            for (; i + 4 <= end; i += 4) {
                int s0 = __ldg(csr + i);
                int s1 = __ldg(csr + i + 1);
                int s2 = __ldg(csr + i + 2);
                int s3 = __ldg(csr + i + 3);
                float4 a = *(const float4*)(h + (size_t)s0 * DIM + cb);
                float4 b = *(const float4*)(h + (size_t)s1 * DIM + cb);
                float4 d = *(const float4*)(h + (size_t)s2 * DIM + cb);
                float4 f = *(const float4*)(h + (size_t)s3 * DIM + cb);
                acc.x += a.x + b.x + d.x + f.x;
                acc.y += a.y + b.y + d.y + f.y;
                acc.z += a.z + b.z + d.z + f.z;
                acc.w += a.w + b.w + d.w + f.w;
            }
            for (; i < end; i++) {
                int s = __ldg(csr + i);
                float4 a = *(const float4*)(h + (size_t)s * DIM + cb);
                acc.x += a.x; acc.y += a.y; acc.z += a.z; acc.w += a.w;
            }
        }
        uint2 hw, lw;
        split4(acc, hw, lw);
        uint32_t o = (uint32_t)(r * LDA) + (uint32_t)(lane * 4);
        *(uint2*)(Ahi + o) = hw;
        *(uint2*)(Alo + o) = lw;
    }
    __syncthreads();

    gemm_mainloop_epilogue(smem, tid, row0, nrows, bias, gamma, beta, mean, var, out);
}

// ---------------- GEMM2: plain A-from-gmem wmma bf16x3 + BN + ReLU ----------
__global__ void __launch_bounds__(NTHREADS, 1)
gemm2_kernel(const float* __restrict__ A,
             const __nv_bfloat16* __restrict__ Bt_hi,
             const __nv_bfloat16* __restrict__ Bt_lo,
             const float* __restrict__ bias,
             const float* __restrict__ gamma,
             const float* __restrict__ beta,
             const float* __restrict__ mean,
             const float* __restrict__ var,
             float* __restrict__ out, int nrows) {
    extern __shared__ char smem[];
    __nv_bfloat16* Ahi = (__nv_bfloat16*)(smem + OFF_AHI);
    __nv_bfloat16* Alo = (__nv_bfloat16*)(smem + OFF_ALO);

    int tid = threadIdx.x;
    int row0 = blockIdx.x * 128;

    stage_B(smem, tid, Bt_hi, Bt_lo);

#pragma unroll
    for (int i = tid; i < 4096; i += NTHREADS) {
        int r = i >> 5;
        int k4 = (i & 31) << 2;
        float4 v = make_float4(0.f, 0.f, 0.f, 0.f);
        if (row0 + r < nrows)
            v = ((const float4*)(A + (size_t)(row0 + r) * DIM))[i & 31];
        uint2 hw, lw;
        split4(v, hw, lw);
        uint32_t o = (uint32_t)(r * LDA + k4);
        *(uint2*)(Ahi + o) = hw;
        *(uint2*)(Alo + o) = lw;
    }
    __syncthreads();

    gemm_mainloop_epilogue(smem, tid, row0, nrows, bias, gamma, beta, mean, var, out);
}

// ---------------- launch ----------------
extern "C" void kernel_launch(void* const* d_in, const int* in_sizes, int n_in,
                              void* d_out, int out_size) {
    const float* x  = (const float*)d_in[0];
    const int*   ei = (const int*)d_in[1];
    const float* W1 = (const float*)d_in[2];
    const float* b1 = (const float*)d_in[3];
    const float* W2 = (const float*)d_in[4];
    const float* b2 = (const float*)d_in[5];
    const float* g  = (const float*)d_in[6];
    const float* be = (const float*)d_in[7];
    const float* rm = (const float*)d_in[8];
    const float* rv = (const float*)d_in[9];

    int N = in_sizes[0] / DIM;
    int E = in_sizes[1] / 2;
    const int* src = ei;
    const int* dst = ei + E;
    float* out = (float*)d_out;

    float *buf0, *buf1;
    int *deg, *off, *cur, *csr, *excl, *bsum, *boff;
    __nv_bfloat16 *wth, *wtl;
    cudaGetSymbolAddress((void**)&buf0, g_buf0);
    cudaGetSymbolAddress((void**)&buf1, g_buf1);
    cudaGetSymbolAddress((void**)&deg, g_deg);
    cudaGetSymbolAddress((void**)&off, g_off);
    cudaGetSymbolAddress((void**)&cur, g_cur);
    cudaGetSymbolAddress((void**)&csr, g_csr);
    cudaGetSymbolAddress((void**)&excl, g_excl);
    cudaGetSymbolAddress((void**)&bsum, g_bsum);
    cudaGetSymbolAddress((void**)&boff, g_boff);
    cudaGetSymbolAddress((void**)&wth, g_wt_hi);
    cudaGetSymbolAddress((void**)&wtl, g_wt_lo);

    cudaFuncSetAttribute(gemm1_fused_kernel,
                         cudaFuncAttributeMaxDynamicSharedMemorySize, SMEM_TOTAL);
    cudaFuncSetAttribute(gemm2_kernel,
                         cudaFuncAttributeMaxDynamicSharedMemorySize, SMEM_TOTAL);

    // weight prep + CSR build
    prep_w_kernel<<<(6 * DIM * DIM + 255) / 256, 256>>>(W1, W2);
    zero_deg_kernel<<<(N + 256) / 256, 256>>>(deg, N);
    hist_kernel<<<(E + 255) / 256, 256>>>(dst, deg, E);
    int nsb = (N + SCAN_CHUNK - 1) / SCAN_CHUNK;
    scan1_kernel<<<nsb, 1024>>>(deg, excl, bsum, N);
    scan2_kernel<<<1, 32>>>(bsum, boff, off, nsb, N);
    scan3_kernel<<<(N + 255) / 256, 256>>>(excl, boff, off, cur, N);
    fill_kernel<<<(E + 255) / 256, 256>>>(src, dst, cur, csr, E);

    // layers: h -> (fused gather+GEMM1) -> o1 -> GEMM2 -> o2
    // L0: h=x    o1=buf1  o2=buf0
    // L1: h=buf0 o1=buf1  o2=buf1? (must not alias) -> o1=buf1, o2 reads o1 only; safe to
    //     reuse buffers as long as a kernel never reads+writes the same one.
    const float* hs[3] = {x, buf0, buf1};
    float* o1s[3]      = {buf1, buf1, buf0};
    float* o2s[3]      = {buf0, buf1, out};
    // L1 check: gemm1 reads buf0, writes buf1 (ok); gemm2 reads buf1, writes buf1 —
    // NOT ok. Fix: L1 o2 = buf1 is invalid; use distinct: L1 o1=buf1, o2 must be != buf1
    // and != buf0 (still needed as input? no — after L1 gemm1, buf0 is dead).
    // Corrected plan:
    //   L0: h=x    o1=buf1 o2=buf0
    //   L1: h=buf0 o1=buf1 o2=buf0   (gemm2 reads buf1 writes buf0: ok, buf0 dead after gemm1)
    //   L2: h=buf0 o1=buf1 o2=out
    const float* hs2[3] = {x, buf0, buf0};
    float* o1s2[3]      = {buf1, buf1, buf1};
    float* o2s2[3]      = {buf0, buf0, out};

    dim3 gmGrid((N + 127) / 128);

    for (int i = 0; i < 3; i++) {
        int w1i = 2 * i, w2i = 2 * i + 1;
        gemm1_fused_kernel<<<gmGrid, NTHREADS, SMEM_TOTAL>>>(
            hs2[i], off, csr,
            wth + (size_t)w1i * DIM * DIM, wtl + (size_t)w1i * DIM * DIM,
            b1 + (size_t)i * DIM,
            g  + (size_t)(2 * i + 0) * DIM, be + (size_t)(2 * i + 0) * DIM,
            rm + (size_t)(2 * i + 0) * DIM, rv + (size_t)(2 * i + 0) * DIM,
            o1s2[i], N);

        gemm2_kernel<<<gmGrid, NTHREADS, SMEM_TOTAL>>>(
            o1s2[i],
            wth + (size_t)w2i * DIM * DIM, wtl + (size_t)w2i * DIM * DIM,
            b2 + (size_t)i * DIM,
            g  + (size_t)(2 * i + 1) * DIM, be + (size_t)(2 * i + 1) * DIM,
            rm + (size_t)(2 * i + 1) * DIM, rv + (size_t)(2 * i + 1) * DIM,
            o2s2[i], N);
    }
}